// round 14
// baseline (speedup 1.0000x reference)
#include <cuda_runtime.h>
#include <cuda_bf16.h>
#include <cuda_fp16.h>
#include <cstdint>

#define EMBED 2048
#define SEQL 4096
#define NH 16
#define NKV 4
#define HD 128
#define KVC (NKV * HD)   // 512
#define WIN 512
// base-2 domain scale: (1/sqrt(128)) * log2(e)
#define SM_SCALE2 (0.08838834764831845f * 1.4426950408889634f)

// ---------------- scratch (allocation-free) ----------------
__device__ __align__(16) __half g_xh[SEQL * EMBED];
// fused fp16 weight arena: rows [wq(2048) | wk(512) | wv(512) | wo(2048)] x 2048
__device__ __align__(16) __half g_w16[(EMBED + 2 * KVC + EMBED) * EMBED];
__device__ float g_bqkv[EMBED + 2 * KVC];             // wq_b | wk_b | wv_b
__device__ __align__(16) __half g_q16[SEQL * EMBED];  // Q fp16
__device__ __align__(16) __half g_k16[SEQL * KVC];    // K fp16
__device__ __align__(16) __half g_v16[SEQL * KVC];    // V fp16
__device__ __align__(16) __half g_c16[SEQL * EMBED];  // ctx fp16

// ---------------- helpers ----------------
__device__ __forceinline__ uint32_t smem_u32(const void* p) {
    uint32_t a;
    asm("{ .reg .u64 t; cvta.to.shared.u64 t, %1; cvt.u32.u64 %0, t; }" : "=r"(a) : "l"(p));
    return a;
}
__device__ __forceinline__ void cpasync16(uint32_t dst, const void* src) {
    asm volatile("cp.async.cg.shared.global [%0], [%1], 16;" :: "r"(dst), "l"(src));
}
__device__ __forceinline__ void ldsm4(uint32_t* r, uint32_t addr) {
    asm volatile("ldmatrix.sync.aligned.m8n8.x4.shared.b16 {%0,%1,%2,%3}, [%4];"
                 : "=r"(r[0]), "=r"(r[1]), "=r"(r[2]), "=r"(r[3]) : "r"(addr));
}
__device__ __forceinline__ void ldsm4t(uint32_t* r, uint32_t addr) {
    asm volatile("ldmatrix.sync.aligned.m8n8.x4.trans.shared.b16 {%0,%1,%2,%3}, [%4];"
                 : "=r"(r[0]), "=r"(r[1]), "=r"(r[2]), "=r"(r[3]) : "r"(addr));
}
__device__ __forceinline__ void mma16816h(float* c, const uint32_t* a, const uint32_t* b) {
    asm volatile("mma.sync.aligned.m16n8k16.row.col.f32.f16.f16.f32 "
                 "{%0,%1,%2,%3}, {%4,%5,%6,%7}, {%8,%9}, {%0,%1,%2,%3};"
                 : "+f"(c[0]), "+f"(c[1]), "+f"(c[2]), "+f"(c[3])
                 : "r"(a[0]), "r"(a[1]), "r"(a[2]), "r"(a[3]), "r"(b[0]), "r"(b[1]));
}
__device__ __forceinline__ float ex2(float x) {
    float r;
    asm("ex2.approx.f32 %0, %1;" : "=f"(r) : "f"(x));
    return r;
}

// ---------------- fused conversion: x + all weights -> fp16 ----------------
#define NX4 (SEQL * EMBED / 4)
#define NQ4 (EMBED * EMBED / 4)
#define NK4 (KVC * EMBED / 4)
#define NTOT4 (NX4 + NQ4 + 2 * NK4 + NQ4)

__global__ __launch_bounds__(256)
void cvt_all_kernel(const float* __restrict__ x,
                    const float* __restrict__ wq, const float* __restrict__ wk,
                    const float* __restrict__ wv, const float* __restrict__ wo,
                    __half* __restrict__ xh, __half* __restrict__ w16) {
    int i = blockIdx.x * blockDim.x + threadIdx.x;
    const int stride = gridDim.x * blockDim.x;
    for (; i < NTOT4; i += stride) {
        const float* src;
        __half* dst;
        int soff, doff;
        if (i < NX4) {
            src = x; soff = i; dst = xh; doff = i;
        } else {
            const int j = i - NX4;
            dst = w16; doff = j;
            if (j < NQ4)                { src = wq; soff = j; }
            else if (j < NQ4 + NK4)     { src = wk; soff = j - NQ4; }
            else if (j < NQ4 + 2 * NK4) { src = wv; soff = j - NQ4 - NK4; }
            else                        { src = wo; soff = j - NQ4 - 2 * NK4; }
        }
        float4 v = ((const float4*)src)[soff];
        __half2 a = __floats2half2_rn(v.x, v.y);
        __half2 b = __floats2half2_rn(v.z, v.w);
        ((__half2*)dst)[2 * doff + 0] = a;
        ((__half2*)dst)[2 * doff + 1] = b;
    }
}

// ---------------- fp16 1-pass GEMM, K-chunk 64, 3-stage single-sync pipeline ----------------
// C[M,N] = A[M,K] @ B[N,K]^T + bias
// fp16 out: Chi (optionally 3-way split at ns1/ns2 into Chi|ChiB|ChiC) or fp32 out C.
#define GBK 64
#define GRS 144                       // 128B data + 16B pad (conflict-free)
#define GTILE_B (128 * GRS)           // 18432
#define GSTAGE_B (2 * GTILE_B)        // 36864 (A, B)
#define GSMEM (3 * GSTAGE_B)          // 110592 -> 2 CTAs/SM

__global__ __launch_bounds__(256, 2)
void gemm_f16_kernel(const __half* __restrict__ Ah,
                     const __half* __restrict__ Bh,
                     const float* __restrict__ bias, float* __restrict__ C,
                     __half* __restrict__ Chi, __half* __restrict__ ChiB,
                     __half* __restrict__ ChiC, int ns1, int ns2,
                     int M, int N, int K) {
    extern __shared__ char dsm[];
    const int tid = threadIdx.x;
    const int wid = tid >> 5, lane = tid & 31;
    const int m0 = blockIdx.y * 128, n0 = blockIdx.x * 128;
    const int wm = (wid >> 2) * 64;
    const int wn = (wid & 3) * 32;
    const int nch = K / GBK;

    // per-CTA fp16 output select
    __half* outh = Chi;
    int ncol0 = n0;
    int ostride = N;
    if (ChiB != nullptr) {
        if (n0 >= ns2)      { outh = ChiC; ncol0 = n0 - ns2; ostride = N - ns2; }
        else if (n0 >= ns1) { outh = ChiB; ncol0 = n0 - ns1; ostride = ns2 - ns1; }
        else                { ostride = ns1; }
    }

    const uint32_t smb = smem_u32(dsm);

    // loader: 2 threads/row; each thread covers 64B (4 x 16B segs) of the 128B row
    const int lrow = tid >> 1;
    const int lhalf = tid & 1;
    const uint32_t ldoff0 = (uint32_t)(lrow * GRS + lhalf * 64);
    const size_t gAoff = (size_t)(m0 + lrow) * K + lhalf * 32;
    const size_t gBoff = (size_t)(n0 + lrow) * K + lhalf * 32;

#define ISSUE_LOAD(c) do { \
        const int _k0 = (c) * GBK; \
        const uint32_t _sb = smb + ((c) % 3) * GSTAGE_B; \
        _Pragma("unroll") \
        for (int _s = 0; _s < 4; _s++) { \
            cpasync16(_sb + ldoff0 + _s * 16,           Ah + gAoff + _k0 + _s * 8); \
            cpasync16(_sb + GTILE_B + ldoff0 + _s * 16, Bh + gBoff + _k0 + _s * 8); \
        } \
    } while (0)

    float acc[4][4][4];
#pragma unroll
    for (int mt = 0; mt < 4; mt++)
#pragma unroll
        for (int nt = 0; nt < 4; nt++)
#pragma unroll
            for (int j = 0; j < 4; j++) acc[mt][nt][j] = 0.0f;

    const uint32_t a_off = (uint32_t)((wm + (lane & 15)) * GRS + ((lane >> 4) << 4));
    const uint32_t b_off = (uint32_t)((wn + (lane >> 4) * 8 + (lane & 7)) * GRS + ((lane >> 3) & 1) * 16);

    // prolog: fill 2 of 3 stages
    ISSUE_LOAD(0);
    asm volatile("cp.async.commit_group;" ::: "memory");
    ISSUE_LOAD(1);
    asm volatile("cp.async.commit_group;" ::: "memory");

    for (int c = 0; c < nch; c++) {
        asm volatile("cp.async.wait_group 1;" ::: "memory");
        __syncthreads();   // chunk c visible to all; all warps done with chunk c-1

        const uint32_t sb = smb + (c % 3) * GSTAGE_B;
        const uint32_t ahb = sb;
        const uint32_t bhb = sb + GTILE_B;

#pragma unroll
        for (int ks = 0; ks < 4; ks++) {
            uint32_t ah[4][4], bh[2][4];
#pragma unroll
            for (int mt = 0; mt < 4; mt++)
                ldsm4(ah[mt], ahb + a_off + mt * (16 * GRS) + ks * 32);
#pragma unroll
            for (int np = 0; np < 2; np++)
                ldsm4(bh[np], bhb + b_off + np * (16 * GRS) + ks * 32);
#pragma unroll
            for (int mt = 0; mt < 4; mt++) {
#pragma unroll
                for (int nt = 0; nt < 4; nt++) {
                    const uint32_t* bhp = &bh[nt >> 1][(nt & 1) * 2];
                    mma16816h(acc[mt][nt], ah[mt], bhp);
                }
            }
        }

        // refill stage (c+2)%3 == (c-1)%3 — all warps finished it before this iteration's sync
        if (c + 2 < nch) ISSUE_LOAD(c + 2);
        asm volatile("cp.async.commit_group;" ::: "memory");
    }

    // epilogue
#pragma unroll
    for (int mt = 0; mt < 4; mt++) {
#pragma unroll
        for (int nt = 0; nt < 4; nt++) {
            const int r = m0 + wm + mt * 16 + (lane >> 2);
            const int cc = n0 + wn + nt * 8 + (lane & 3) * 2;
            const float b0 = bias[cc], b1 = bias[cc + 1];
            float o0 = acc[mt][nt][0] + b0, o1 = acc[mt][nt][1] + b1;
            float o2 = acc[mt][nt][2] + b0, o3 = acc[mt][nt][3] + b1;
            if (Chi) {
                const int lc = ncol0 + wn + nt * 8 + (lane & 3) * 2;
                __half2 h01 = __floats2half2_rn(o0, o1);
                __half2 h23 = __floats2half2_rn(o2, o3);
                *(__half2*)&outh[(size_t)r * ostride + lc] = h01;
                *(__half2*)&outh[(size_t)(r + 8) * ostride + lc] = h23;
            } else {
                *(float2*)&C[(size_t)r * N + cc] = make_float2(o0, o1);
                *(float2*)&C[(size_t)(r + 8) * N + cc] = make_float2(o2, o3);
            }
        }
    }
#undef ISSUE_LOAD
}

// ---------------- fp16 1-pass sliding-window attention, fixed-shift softmax ----------------
#define AQ 128
#define AK 64
#define ARS 272
#define ATILE (64 * ARS)              // 17408
#define AQTILE (128 * ARS)            // 34816
#define AKV_STAGE (2 * ATILE)         // 34816 (Kh, Vh)
#define ASMEM (AQTILE + 2 * AKV_STAGE)  // 104448 -> 2 CTAs/SM

__global__ __launch_bounds__(256, 2)
void attn_mma_kernel(const __half* __restrict__ Qg,
                     const __half* __restrict__ Kg, const __half* __restrict__ Vg,
                     __half* __restrict__ Ch) {
    extern __shared__ char sm_[];
    const int tid = threadIdx.x, wid = tid >> 5, lane = tid & 31;
    const int h = blockIdx.y;
    const int q0 = blockIdx.x * AQ;
    const int kvh = h >> 2;

    const uint32_t smb = smem_u32(sm_);
    const uint32_t qh_b = smb;
    const uint32_t kv_b = smb + AQTILE;

    // Q loads: 128 rows x 256B; 2 threads/row, 8 segs each
    {
        const int row = tid >> 1;
        const int s0 = (tid & 1) * 8;
        const __half* gq = Qg + (size_t)(q0 + row) * EMBED + h * HD + s0 * 8;
        const uint32_t soff = (uint32_t)(row * ARS + s0 * 16);
#pragma unroll
        for (int s = 0; s < 8; s++) cpasync16(qh_b + soff + s * 16, gq + s * 8);
    }

    // KV loader: lt = tid>>7 (0=K,1=V); 2 threads/row, 8 segs each
    const int lt = tid >> 7;
    const int lrow = (tid >> 1) & 63;
    const int lseg = (tid & 1) * 8;
    const __half* ltp = lt ? Vg : Kg;
    const uint32_t lso = (uint32_t)(lt * ATILE + lrow * ARS + lseg * 16);

#define ISSUE_KV(kt, stage) do { \
        const __half* _g = ltp + (size_t)((kt) * AK + lrow) * KVC + kvh * HD + lseg * 8; \
        const uint32_t _sb = kv_b + (stage) * AKV_STAGE + lso; \
        _Pragma("unroll") \
        for (int _s = 0; _s < 8; _s++) cpasync16(_sb + _s * 16, _g + _s * 8); \
    } while (0)

    const int ktS = (q0 >= WIN) ? ((q0 - WIN) >> 6) : 0;
    const int ktE = (q0 + AQ - 64) >> 6;

    ISSUE_KV(ktS, 0);
    asm volatile("cp.async.commit_group;" ::: "memory");
    if (ktS + 1 <= ktE) ISSUE_KV(ktS + 1, 1);
    asm volatile("cp.async.commit_group;" ::: "memory");
    asm volatile("cp.async.wait_group 1;" ::: "memory");
    __syncthreads();

    const uint32_t a_off = (uint32_t)((wid * 16 + (lane & 15)) * ARS + ((lane >> 4) << 4));
    const uint32_t b_off = (uint32_t)(((lane & 7) + ((lane >> 4) << 3)) * ARS + ((lane >> 3) & 1) * 16);
    const uint32_t v_off = (uint32_t)((lane & 15) * ARS + ((lane >> 4) << 4));

    float l0r = 0.0f, l1r = 0.0f;
    float O[16][4];
#pragma unroll
    for (int i = 0; i < 16; i++)
#pragma unroll
        for (int j = 0; j < 4; j++) O[i][j] = 0.0f;

    const int qi0 = q0 + wid * 16 + (lane >> 2);
    const int qi1 = qi0 + 8;

    for (int kt = ktS; kt <= ktE; kt++) {
        const int stage = (kt - ktS) & 1;
        const uint32_t kh_b = kv_b + stage * AKV_STAGE;
        const uint32_t vh_b = kh_b + ATILE;
        const int k0 = kt * AK;

        // ---- S = Q Kh^T (1-pass) ----
        float sc[8][4];
#pragma unroll
        for (int i = 0; i < 8; i++)
#pragma unroll
            for (int j = 0; j < 4; j++) sc[i][j] = 0.0f;

#pragma unroll
        for (int ks = 0; ks < 8; ks++) {
            uint32_t qa[4];
            ldsm4(qa, qh_b + a_off + ks * 32);
#pragma unroll
            for (int np = 0; np < 4; np++) {
                uint32_t kh4[4];
                ldsm4(kh4, kh_b + b_off + np * (16 * ARS) + ks * 32);
                mma16816h(sc[2 * np], qa, &kh4[0]);
                mma16816h(sc[2 * np + 1], qa, &kh4[2]);
            }
        }

        // ---- mask + scale + exp2 (fixed shift) ----
        float ls0 = 0.0f, ls1 = 0.0f;
#pragma unroll
        for (int nt = 0; nt < 8; nt++) {
            const int kib = k0 + nt * 8 + (lane & 3) * 2;
#pragma unroll
            for (int j = 0; j < 4; j++) {
                const int kij = kib + (j & 1);
                const int qij = (j >> 1) ? qi1 : qi0;
                const bool ok = (kij <= qij) && (kij + WIN >= qij);
                sc[nt][j] = ex2(ok ? sc[nt][j] * SM_SCALE2 : -10000.0f);
            }
            ls0 += sc[nt][0] + sc[nt][1];
            ls1 += sc[nt][2] + sc[nt][3];
        }
        l0r += ls0; l1r += ls1;

        // ---- pack P (single fp16) into A-fragments ----
        uint32_t pah[4][4];
#pragma unroll
        for (int ks = 0; ks < 4; ks++) {
            __half2 p0 = __floats2half2_rn(sc[2 * ks][0], sc[2 * ks][1]);
            __half2 p1 = __floats2half2_rn(sc[2 * ks][2], sc[2 * ks][3]);
            __half2 p2 = __floats2half2_rn(sc[2 * ks + 1][0], sc[2 * ks + 1][1]);
            __half2 p3 = __floats2half2_rn(sc[2 * ks + 1][2], sc[2 * ks + 1][3]);
            pah[ks][0] = *(uint32_t*)&p0;
            pah[ks][1] = *(uint32_t*)&p1;
            pah[ks][2] = *(uint32_t*)&p2;
            pah[ks][3] = *(uint32_t*)&p3;
        }

        // ---- O += P Vh (1-pass) ----
#pragma unroll
        for (int ks = 0; ks < 4; ks++) {
#pragma unroll
            for (int dp = 0; dp < 8; dp++) {
                uint32_t vh4[4];
                ldsm4t(vh4, vh_b + v_off + ks * (16 * ARS) + dp * 32);
                mma16816h(O[2 * dp], pah[ks], &vh4[0]);
                mma16816h(O[2 * dp + 1], pah[ks], &vh4[2]);
            }
        }

        // ---- pipeline ----
        __syncthreads();
        if (kt + 2 <= ktE) ISSUE_KV(kt + 2, stage);
        asm volatile("cp.async.commit_group;" ::: "memory");
        if (kt + 2 <= ktE) asm volatile("cp.async.wait_group 1;" ::: "memory");
        else               asm volatile("cp.async.wait_group 0;" ::: "memory");
        __syncthreads();
    }
#undef ISSUE_KV

    l0r += __shfl_xor_sync(0xffffffffu, l0r, 1);
    l0r += __shfl_xor_sync(0xffffffffu, l0r, 2);
    l1r += __shfl_xor_sync(0xffffffffu, l1r, 1);
    l1r += __shfl_xor_sync(0xffffffffu, l1r, 2);
    const float inv0 = 1.0f / l0r, inv1 = 1.0f / l1r;
    const size_t r0off = (size_t)qi0 * EMBED + h * HD;
    const size_t r1off = (size_t)qi1 * EMBED + h * HD;
#pragma unroll
    for (int nt = 0; nt < 16; nt++) {
        const int d = nt * 8 + (lane & 3) * 2;
        __half2 c0 = __floats2half2_rn(O[nt][0] * inv0, O[nt][1] * inv0);
        __half2 c1 = __floats2half2_rn(O[nt][2] * inv1, O[nt][3] * inv1);
        *(__half2*)&Ch[r0off + d] = c0;
        *(__half2*)&Ch[r1off + d] = c1;
    }
}

// ---------------- launch ----------------
extern "C" void kernel_launch(void* const* d_in, const int* in_sizes, int n_in,
                              void* d_out, int out_size) {
    const float* x    = (const float*)d_in[0];
    const float* wq_w = (const float*)d_in[1];
    const float* wq_b = (const float*)d_in[2];
    const float* wk_w = (const float*)d_in[3];
    const float* wk_b = (const float*)d_in[4];
    const float* wv_w = (const float*)d_in[5];
    const float* wv_b = (const float*)d_in[6];
    const float* wo_w = (const float*)d_in[7];
    const float* wo_b = (const float*)d_in[8];
    float* out = (float*)d_out;

    __half *xh, *w16, *q16, *k16, *v16, *c16;
    float* bqkv;
    cudaGetSymbolAddress((void**)&xh, g_xh);
    cudaGetSymbolAddress((void**)&w16, g_w16);
    cudaGetSymbolAddress((void**)&bqkv, g_bqkv);
    cudaGetSymbolAddress((void**)&q16, g_q16);
    cudaGetSymbolAddress((void**)&k16, g_k16);
    cudaGetSymbolAddress((void**)&v16, g_v16);
    cudaGetSymbolAddress((void**)&c16, g_c16);

    cudaFuncSetAttribute(gemm_f16_kernel, cudaFuncAttributeMaxDynamicSharedMemorySize, GSMEM);
    cudaFuncSetAttribute(attn_mma_kernel, cudaFuncAttributeMaxDynamicSharedMemorySize, ASMEM);

    // fused QKV bias (device-to-device, graph-capturable)
    cudaMemcpyAsync(bqkv, wq_b, EMBED * sizeof(float), cudaMemcpyDeviceToDevice);
    cudaMemcpyAsync(bqkv + EMBED, wk_b, KVC * sizeof(float), cudaMemcpyDeviceToDevice);
    cudaMemcpyAsync(bqkv + EMBED + KVC, wv_b, KVC * sizeof(float), cudaMemcpyDeviceToDevice);

    // single fused conversion: x + all weights -> fp16
    cvt_all_kernel<<<2048, 256>>>(x, wq_w, wk_w, wv_w, wo_w, xh, w16);

    dim3 blk(256);
    // fused Q+K+V projection: 1-pass, 3-way split fp16 outputs
    gemm_f16_kernel<<<dim3((EMBED + 2 * KVC) / 128, SEQL / 128), blk, GSMEM>>>(
        xh, w16, bqkv, nullptr, q16, k16, v16, EMBED, EMBED + KVC,
        SEQL, EMBED + 2 * KVC, EMBED);

    attn_mma_kernel<<<dim3(SEQL / AQ, NH), blk, ASMEM>>>(q16, k16, v16, c16);

    // O-proj: 1-pass, fp32 output
    gemm_f16_kernel<<<dim3(EMBED / 128, SEQL / 128), blk, GSMEM>>>(
        c16, w16 + (size_t)(EMBED + 2 * KVC) * EMBED, wo_b, out,
        nullptr, nullptr, nullptr, 0, 0, SEQL, EMBED, EMBED);
}

// round 15
// speedup vs baseline: 1.0854x; 1.0854x over previous
#include <cuda_runtime.h>
#include <cuda_bf16.h>
#include <cuda_fp16.h>
#include <cstdint>

#define EMBED 2048
#define SEQL 4096
#define NH 16
#define NKV 4
#define HD 128
#define KVC (NKV * HD)   // 512
#define WIN 512
// base-2 domain scale: (1/sqrt(128)) * log2(e)
#define SM_SCALE2 (0.08838834764831845f * 1.4426950408889634f)

// ---------------- scratch (allocation-free) ----------------
__device__ __align__(16) __half g_xh[SEQL * EMBED];
// fused fp16 weight arena: rows [wq(2048) | wk(512) | wv(512) | wo(2048)] x 2048
__device__ __align__(16) __half g_w16[(EMBED + 2 * KVC + EMBED) * EMBED];
__device__ float g_bqkv[EMBED + 2 * KVC];             // wq_b | wk_b | wv_b
__device__ __align__(16) __half g_q16[SEQL * EMBED];  // Q fp16
__device__ __align__(16) __half g_k16[SEQL * KVC];    // K fp16
__device__ __align__(16) __half g_v16[SEQL * KVC];    // V fp16
__device__ __align__(16) __half g_c16[SEQL * EMBED];  // ctx fp16

// ---------------- helpers ----------------
__device__ __forceinline__ uint32_t smem_u32(const void* p) {
    uint32_t a;
    asm("{ .reg .u64 t; cvta.to.shared.u64 t, %1; cvt.u32.u64 %0, t; }" : "=r"(a) : "l"(p));
    return a;
}
__device__ __forceinline__ void cpasync16(uint32_t dst, const void* src) {
    asm volatile("cp.async.cg.shared.global [%0], [%1], 16;" :: "r"(dst), "l"(src));
}
__device__ __forceinline__ void ldsm4(uint32_t* r, uint32_t addr) {
    asm volatile("ldmatrix.sync.aligned.m8n8.x4.shared.b16 {%0,%1,%2,%3}, [%4];"
                 : "=r"(r[0]), "=r"(r[1]), "=r"(r[2]), "=r"(r[3]) : "r"(addr));
}
__device__ __forceinline__ void ldsm4t(uint32_t* r, uint32_t addr) {
    asm volatile("ldmatrix.sync.aligned.m8n8.x4.trans.shared.b16 {%0,%1,%2,%3}, [%4];"
                 : "=r"(r[0]), "=r"(r[1]), "=r"(r[2]), "=r"(r[3]) : "r"(addr));
}
__device__ __forceinline__ void mma16816h(float* c, const uint32_t* a, const uint32_t* b) {
    asm volatile("mma.sync.aligned.m16n8k16.row.col.f32.f16.f16.f32 "
                 "{%0,%1,%2,%3}, {%4,%5,%6,%7}, {%8,%9}, {%0,%1,%2,%3};"
                 : "+f"(c[0]), "+f"(c[1]), "+f"(c[2]), "+f"(c[3])
                 : "r"(a[0]), "r"(a[1]), "r"(a[2]), "r"(a[3]), "r"(b[0]), "r"(b[1]));
}
__device__ __forceinline__ float ex2(float x) {
    float r;
    asm("ex2.approx.f32 %0, %1;" : "=f"(r) : "f"(x));
    return r;
}

// ---------------- fused conversion: x + all weights -> fp16 ----------------
#define NX4 (SEQL * EMBED / 4)
#define NQ4 (EMBED * EMBED / 4)
#define NK4 (KVC * EMBED / 4)
#define NTOT4 (NX4 + NQ4 + 2 * NK4 + NQ4)

__global__ __launch_bounds__(256)
void cvt_all_kernel(const float* __restrict__ x,
                    const float* __restrict__ wq, const float* __restrict__ wk,
                    const float* __restrict__ wv, const float* __restrict__ wo,
                    __half* __restrict__ xh, __half* __restrict__ w16) {
    int i = blockIdx.x * blockDim.x + threadIdx.x;
    const int stride = gridDim.x * blockDim.x;
    for (; i < NTOT4; i += stride) {
        const float* src;
        __half* dst;
        int soff, doff;
        if (i < NX4) {
            src = x; soff = i; dst = xh; doff = i;
        } else {
            const int j = i - NX4;
            dst = w16; doff = j;
            if (j < NQ4)                { src = wq; soff = j; }
            else if (j < NQ4 + NK4)     { src = wk; soff = j - NQ4; }
            else if (j < NQ4 + 2 * NK4) { src = wv; soff = j - NQ4 - NK4; }
            else                        { src = wo; soff = j - NQ4 - 2 * NK4; }
        }
        float4 v = ((const float4*)src)[soff];
        __half2 a = __floats2half2_rn(v.x, v.y);
        __half2 b = __floats2half2_rn(v.z, v.w);
        ((__half2*)dst)[2 * doff + 0] = a;
        ((__half2*)dst)[2 * doff + 1] = b;
    }
}

// ---------------- fp16 1-pass GEMM, 5-stage single-sync pipeline ----------------
// C[M,N] = A[M,K] @ B[N,K]^T + bias
// fp16 out: Chi (optionally 3-way split at ns1/ns2 into Chi|ChiB|ChiC) or fp32 out C.
#define GBK 32
#define GRS 80
#define GTILE_B (128 * GRS)          // 10240
#define GSTAGE_B (2 * GTILE_B)       // 20480 (A, B)
#define GSTAGES 5
#define GSMEM (GSTAGES * GSTAGE_B)   // 102400 -> 2 CTAs/SM

__global__ __launch_bounds__(256, 2)
void gemm_f16_kernel(const __half* __restrict__ Ah,
                     const __half* __restrict__ Bh,
                     const float* __restrict__ bias, float* __restrict__ C,
                     __half* __restrict__ Chi, __half* __restrict__ ChiB,
                     __half* __restrict__ ChiC, int ns1, int ns2,
                     int M, int N, int K) {
    extern __shared__ char dsm[];
    const int tid = threadIdx.x;
    const int wid = tid >> 5, lane = tid & 31;
    const int m0 = blockIdx.y * 128, n0 = blockIdx.x * 128;
    const int wm = (wid >> 2) * 64;
    const int wn = (wid & 3) * 32;
    const int nch = K / GBK;

    // per-CTA fp16 output select
    __half* outh = Chi;
    int ncol0 = n0;
    int ostride = N;
    if (ChiB != nullptr) {
        if (n0 >= ns2)      { outh = ChiC; ncol0 = n0 - ns2; ostride = N - ns2; }
        else if (n0 >= ns1) { outh = ChiB; ncol0 = n0 - ns1; ostride = ns2 - ns1; }
        else                { ostride = ns1; }
    }

    const uint32_t smb = smem_u32(dsm);

    const int rem0 = tid * 2;
    const int lrow = rem0 >> 2;
    const int lcg = rem0 & 3;
    const uint32_t ldoff0 = (uint32_t)(lrow * GRS + lcg * 16);
    const size_t gAoff = (size_t)(m0 + lrow) * K + lcg * 8;
    const size_t gBoff = (size_t)(n0 + lrow) * K + lcg * 8;

#define ISSUE_LOAD(c) do { \
        const int _k0 = (c) * GBK; \
        const uint32_t _sb = smb + ((c) % GSTAGES) * GSTAGE_B; \
        cpasync16(_sb + ldoff0,                Ah + gAoff + _k0); \
        cpasync16(_sb + ldoff0 + 16,           Ah + gAoff + _k0 + 8); \
        cpasync16(_sb + GTILE_B + ldoff0,      Bh + gBoff + _k0); \
        cpasync16(_sb + GTILE_B + ldoff0 + 16, Bh + gBoff + _k0 + 8); \
    } while (0)

    float acc[4][4][4];
#pragma unroll
    for (int mt = 0; mt < 4; mt++)
#pragma unroll
        for (int nt = 0; nt < 4; nt++)
#pragma unroll
            for (int j = 0; j < 4; j++) acc[mt][nt][j] = 0.0f;

    const uint32_t a_off = (uint32_t)((wm + (lane & 15)) * GRS + ((lane >> 4) << 4));
    const uint32_t b_off = (uint32_t)((wn + (lane >> 4) * 8 + (lane & 7)) * GRS + ((lane >> 3) & 1) * 16);

    // prolog: fill 4 of 5 stages (one commit group each)
    ISSUE_LOAD(0);
    asm volatile("cp.async.commit_group;" ::: "memory");
    ISSUE_LOAD(1);
    asm volatile("cp.async.commit_group;" ::: "memory");
    ISSUE_LOAD(2);
    asm volatile("cp.async.commit_group;" ::: "memory");
    ISSUE_LOAD(3);
    asm volatile("cp.async.commit_group;" ::: "memory");

    for (int c = 0; c < nch; c++) {
        // commits so far = 4 + c; waiting for <=3 pending ensures chunks 0..c landed
        asm volatile("cp.async.wait_group 3;" ::: "memory");
        __syncthreads();   // chunk c visible to all warps; all warps done with chunk c-1

        const uint32_t sb = smb + (c % GSTAGES) * GSTAGE_B;
        const uint32_t ahb = sb;
        const uint32_t bhb = sb + GTILE_B;

#pragma unroll
        for (int ks = 0; ks < 2; ks++) {
            uint32_t ah[4][4], bh[2][4];
#pragma unroll
            for (int mt = 0; mt < 4; mt++)
                ldsm4(ah[mt], ahb + a_off + mt * (16 * GRS) + ks * 32);
#pragma unroll
            for (int np = 0; np < 2; np++)
                ldsm4(bh[np], bhb + b_off + np * (16 * GRS) + ks * 32);
#pragma unroll
            for (int mt = 0; mt < 4; mt++) {
#pragma unroll
                for (int nt = 0; nt < 4; nt++) {
                    const uint32_t* bhp = &bh[nt >> 1][(nt & 1) * 2];
                    mma16816h(acc[mt][nt], ah[mt], bhp);
                }
            }
        }

        // refill stage (c+4)%5 == (c-1)%5 — all warps finished it before this iteration's sync
        if (c + 4 < nch) ISSUE_LOAD(c + 4);
        asm volatile("cp.async.commit_group;" ::: "memory");
    }

    // epilogue
#pragma unroll
    for (int mt = 0; mt < 4; mt++) {
#pragma unroll
        for (int nt = 0; nt < 4; nt++) {
            const int r = m0 + wm + mt * 16 + (lane >> 2);
            const int cc = n0 + wn + nt * 8 + (lane & 3) * 2;
            const float b0 = bias[cc], b1 = bias[cc + 1];
            float o0 = acc[mt][nt][0] + b0, o1 = acc[mt][nt][1] + b1;
            float o2 = acc[mt][nt][2] + b0, o3 = acc[mt][nt][3] + b1;
            if (Chi) {
                const int lc = ncol0 + wn + nt * 8 + (lane & 3) * 2;
                __half2 h01 = __floats2half2_rn(o0, o1);
                __half2 h23 = __floats2half2_rn(o2, o3);
                *(__half2*)&outh[(size_t)r * ostride + lc] = h01;
                *(__half2*)&outh[(size_t)(r + 8) * ostride + lc] = h23;
            } else {
                *(float2*)&C[(size_t)r * N + cc] = make_float2(o0, o1);
                *(float2*)&C[(size_t)(r + 8) * N + cc] = make_float2(o2, o3);
            }
        }
    }
#undef ISSUE_LOAD
}

// ---------------- fp16 1-pass sliding-window attention, fixed-shift softmax ----------------
#define AQ 128
#define AK 64
#define ARS 272
#define ATILE (64 * ARS)              // 17408
#define AQTILE (128 * ARS)            // 34816
#define AKV_STAGE (2 * ATILE)         // 34816 (Kh, Vh)
#define ASMEM (AQTILE + 2 * AKV_STAGE)  // 104448 -> 2 CTAs/SM

__global__ __launch_bounds__(256, 2)
void attn_mma_kernel(const __half* __restrict__ Qg,
                     const __half* __restrict__ Kg, const __half* __restrict__ Vg,
                     __half* __restrict__ Ch) {
    extern __shared__ char sm_[];
    const int tid = threadIdx.x, wid = tid >> 5, lane = tid & 31;
    const int h = blockIdx.y;
    const int q0 = blockIdx.x * AQ;
    const int kvh = h >> 2;

    const uint32_t smb = smem_u32(sm_);
    const uint32_t qh_b = smb;
    const uint32_t kv_b = smb + AQTILE;

    // Q loads: 128 rows x 256B; 2 threads/row, 8 segs each
    {
        const int row = tid >> 1;
        const int s0 = (tid & 1) * 8;
        const __half* gq = Qg + (size_t)(q0 + row) * EMBED + h * HD + s0 * 8;
        const uint32_t soff = (uint32_t)(row * ARS + s0 * 16);
#pragma unroll
        for (int s = 0; s < 8; s++) cpasync16(qh_b + soff + s * 16, gq + s * 8);
    }

    // KV loader: lt = tid>>7 (0=K,1=V); 2 threads/row, 8 segs each
    const int lt = tid >> 7;
    const int lrow = (tid >> 1) & 63;
    const int lseg = (tid & 1) * 8;
    const __half* ltp = lt ? Vg : Kg;
    const uint32_t lso = (uint32_t)(lt * ATILE + lrow * ARS + lseg * 16);

#define ISSUE_KV(kt, stage) do { \
        const __half* _g = ltp + (size_t)((kt) * AK + lrow) * KVC + kvh * HD + lseg * 8; \
        const uint32_t _sb = kv_b + (stage) * AKV_STAGE + lso; \
        _Pragma("unroll") \
        for (int _s = 0; _s < 8; _s++) cpasync16(_sb + _s * 16, _g + _s * 8); \
    } while (0)

    const int ktS = (q0 >= WIN) ? ((q0 - WIN) >> 6) : 0;
    const int ktE = (q0 + AQ - 64) >> 6;

    ISSUE_KV(ktS, 0);
    asm volatile("cp.async.commit_group;" ::: "memory");
    if (ktS + 1 <= ktE) ISSUE_KV(ktS + 1, 1);
    asm volatile("cp.async.commit_group;" ::: "memory");
    asm volatile("cp.async.wait_group 1;" ::: "memory");
    __syncthreads();

    const uint32_t a_off = (uint32_t)((wid * 16 + (lane & 15)) * ARS + ((lane >> 4) << 4));
    const uint32_t b_off = (uint32_t)(((lane & 7) + ((lane >> 4) << 3)) * ARS + ((lane >> 3) & 1) * 16);
    const uint32_t v_off = (uint32_t)((lane & 15) * ARS + ((lane >> 4) << 4));

    float l0r = 0.0f, l1r = 0.0f;
    float O[16][4];
#pragma unroll
    for (int i = 0; i < 16; i++)
#pragma unroll
        for (int j = 0; j < 4; j++) O[i][j] = 0.0f;

    const int qi0 = q0 + wid * 16 + (lane >> 2);
    const int qi1 = qi0 + 8;

    for (int kt = ktS; kt <= ktE; kt++) {
        const int stage = (kt - ktS) & 1;
        const uint32_t kh_b = kv_b + stage * AKV_STAGE;
        const uint32_t vh_b = kh_b + ATILE;
        const int k0 = kt * AK;

        // ---- S = Q Kh^T (1-pass) ----
        float sc[8][4];
#pragma unroll
        for (int i = 0; i < 8; i++)
#pragma unroll
            for (int j = 0; j < 4; j++) sc[i][j] = 0.0f;

#pragma unroll
        for (int ks = 0; ks < 8; ks++) {
            uint32_t qa[4];
            ldsm4(qa, qh_b + a_off + ks * 32);
#pragma unroll
            for (int np = 0; np < 4; np++) {
                uint32_t kh4[4];
                ldsm4(kh4, kh_b + b_off + np * (16 * ARS) + ks * 32);
                mma16816h(sc[2 * np], qa, &kh4[0]);
                mma16816h(sc[2 * np + 1], qa, &kh4[2]);
            }
        }

        // ---- mask + scale + exp2 (fixed shift) ----
        float ls0 = 0.0f, ls1 = 0.0f;
#pragma unroll
        for (int nt = 0; nt < 8; nt++) {
            const int kib = k0 + nt * 8 + (lane & 3) * 2;
#pragma unroll
            for (int j = 0; j < 4; j++) {
                const int kij = kib + (j & 1);
                const int qij = (j >> 1) ? qi1 : qi0;
                const bool ok = (kij <= qij) && (kij + WIN >= qij);
                sc[nt][j] = ex2(ok ? sc[nt][j] * SM_SCALE2 : -10000.0f);
            }
            ls0 += sc[nt][0] + sc[nt][1];
            ls1 += sc[nt][2] + sc[nt][3];
        }
        l0r += ls0; l1r += ls1;

        // ---- pack P (single fp16) into A-fragments ----
        uint32_t pah[4][4];
#pragma unroll
        for (int ks = 0; ks < 4; ks++) {
            __half2 p0 = __floats2half2_rn(sc[2 * ks][0], sc[2 * ks][1]);
            __half2 p1 = __floats2half2_rn(sc[2 * ks][2], sc[2 * ks][3]);
            __half2 p2 = __floats2half2_rn(sc[2 * ks + 1][0], sc[2 * ks + 1][1]);
            __half2 p3 = __floats2half2_rn(sc[2 * ks + 1][2], sc[2 * ks + 1][3]);
            pah[ks][0] = *(uint32_t*)&p0;
            pah[ks][1] = *(uint32_t*)&p1;
            pah[ks][2] = *(uint32_t*)&p2;
            pah[ks][3] = *(uint32_t*)&p3;
        }

        // ---- O += P Vh (1-pass) ----
#pragma unroll
        for (int ks = 0; ks < 4; ks++) {
#pragma unroll
            for (int dp = 0; dp < 8; dp++) {
                uint32_t vh4[4];
                ldsm4t(vh4, vh_b + v_off + ks * (16 * ARS) + dp * 32);
                mma16816h(O[2 * dp], pah[ks], &vh4[0]);
                mma16816h(O[2 * dp + 1], pah[ks], &vh4[2]);
            }
        }

        // ---- pipeline ----
        __syncthreads();
        if (kt + 2 <= ktE) ISSUE_KV(kt + 2, stage);
        asm volatile("cp.async.commit_group;" ::: "memory");
        if (kt + 2 <= ktE) asm volatile("cp.async.wait_group 1;" ::: "memory");
        else               asm volatile("cp.async.wait_group 0;" ::: "memory");
        __syncthreads();
    }
#undef ISSUE_KV

    l0r += __shfl_xor_sync(0xffffffffu, l0r, 1);
    l0r += __shfl_xor_sync(0xffffffffu, l0r, 2);
    l1r += __shfl_xor_sync(0xffffffffu, l1r, 1);
    l1r += __shfl_xor_sync(0xffffffffu, l1r, 2);
    const float inv0 = 1.0f / l0r, inv1 = 1.0f / l1r;
    const size_t r0off = (size_t)qi0 * EMBED + h * HD;
    const size_t r1off = (size_t)qi1 * EMBED + h * HD;
#pragma unroll
    for (int nt = 0; nt < 16; nt++) {
        const int d = nt * 8 + (lane & 3) * 2;
        __half2 c0 = __floats2half2_rn(O[nt][0] * inv0, O[nt][1] * inv0);
        __half2 c1 = __floats2half2_rn(O[nt][2] * inv1, O[nt][3] * inv1);
        *(__half2*)&Ch[r0off + d] = c0;
        *(__half2*)&Ch[r1off + d] = c1;
    }
}

// ---------------- launch ----------------
extern "C" void kernel_launch(void* const* d_in, const int* in_sizes, int n_in,
                              void* d_out, int out_size) {
    const float* x    = (const float*)d_in[0];
    const float* wq_w = (const float*)d_in[1];
    const float* wq_b = (const float*)d_in[2];
    const float* wk_w = (const float*)d_in[3];
    const float* wk_b = (const float*)d_in[4];
    const float* wv_w = (const float*)d_in[5];
    const float* wv_b = (const float*)d_in[6];
    const float* wo_w = (const float*)d_in[7];
    const float* wo_b = (const float*)d_in[8];
    float* out = (float*)d_out;

    __half *xh, *w16, *q16, *k16, *v16, *c16;
    float* bqkv;
    cudaGetSymbolAddress((void**)&xh, g_xh);
    cudaGetSymbolAddress((void**)&w16, g_w16);
    cudaGetSymbolAddress((void**)&bqkv, g_bqkv);
    cudaGetSymbolAddress((void**)&q16, g_q16);
    cudaGetSymbolAddress((void**)&k16, g_k16);
    cudaGetSymbolAddress((void**)&v16, g_v16);
    cudaGetSymbolAddress((void**)&c16, g_c16);

    cudaFuncSetAttribute(gemm_f16_kernel, cudaFuncAttributeMaxDynamicSharedMemorySize, GSMEM);
    cudaFuncSetAttribute(attn_mma_kernel, cudaFuncAttributeMaxDynamicSharedMemorySize, ASMEM);

    // fused QKV bias (device-to-device, graph-capturable)
    cudaMemcpyAsync(bqkv, wq_b, EMBED * sizeof(float), cudaMemcpyDeviceToDevice);
    cudaMemcpyAsync(bqkv + EMBED, wk_b, KVC * sizeof(float), cudaMemcpyDeviceToDevice);
    cudaMemcpyAsync(bqkv + EMBED + KVC, wv_b, KVC * sizeof(float), cudaMemcpyDeviceToDevice);

    // single fused conversion: x + all weights -> fp16
    cvt_all_kernel<<<2048, 256>>>(x, wq_w, wk_w, wv_w, wo_w, xh, w16);

    dim3 blk(256);
    // fused Q+K+V projection: 1-pass, 3-way split fp16 outputs
    gemm_f16_kernel<<<dim3((EMBED + 2 * KVC) / 128, SEQL / 128), blk, GSMEM>>>(
        xh, w16, bqkv, nullptr, q16, k16, v16, EMBED, EMBED + KVC,
        SEQL, EMBED + 2 * KVC, EMBED);

    attn_mma_kernel<<<dim3(SEQL / AQ, NH), blk, ASMEM>>>(q16, k16, v16, c16);

    // O-proj: 1-pass, fp32 output
    gemm_f16_kernel<<<dim3(EMBED / 128, SEQL / 128), blk, GSMEM>>>(
        c16, w16 + (size_t)(EMBED + 2 * KVC) * EMBED, wo_b, out,
        nullptr, nullptr, nullptr, 0, 0, SEQL, EMBED, EMBED);
}